// round 1
// baseline (speedup 1.0000x reference)
#include <cuda_runtime.h>

// Problem dims
#define SQ 2048
#define DM 1024
#define NH 16
#define DKH 64
#define NHID (NH*DKH)   // 1024

// Scratch (allowed: __device__ globals, no runtime allocation)
__device__ float g_q[NH*SQ*DKH];
__device__ float g_k[NH*SQ*DKH];
__device__ float g_v[NH*SQ*DKH];
__device__ float g_concat[SQ*NHID];

// ---------------------------------------------------------------------------
// Projection GEMM: C[h,s,k] = sum_d A[s,d] * W[h,d,k] + bias[h,k]
// Block computes a 64x64 tile of the logical [S, H*DK] output; since BN==DK,
// each block maps to exactly one head.
// ---------------------------------------------------------------------------
__global__ __launch_bounds__(256) void proj_gemm_kernel(
    const float* __restrict__ A,      // [S, D]
    const float* __restrict__ W,      // [H, D, DK]
    const float* __restrict__ bias,   // [H*DK]
    float* __restrict__ C)            // [H, S, DK]
{
    __shared__ float As[16][65];   // transposed A tile, padded
    __shared__ float Bs[16][64];   // natural B tile

    const int tid = threadIdx.x;
    const int tx = tid & 15;
    const int ty = tid >> 4;
    const int m0 = blockIdx.y * 64;
    const int n0 = blockIdx.x * 64;
    const int head = n0 >> 6;
    const float* Wh = W + (size_t)head * DM * DKH;

    float acc[4][4];
#pragma unroll
    for (int r = 0; r < 4; r++)
#pragma unroll
        for (int c = 0; c < 4; c++) acc[r][c] = 0.f;

    for (int k0 = 0; k0 < DM; k0 += 16) {
        // A tile: 64 rows x 16 k, store transposed As[kk][m]
#pragma unroll
        for (int j = 0; j < 4; j++) {
            int i = tid + j * 256;            // 0..1023
            int m = i >> 4, kk = i & 15;
            As[kk][m] = A[(size_t)(m0 + m) * DM + k0 + kk];
        }
        // B tile: 16 k x 64 n (contiguous within head)
#pragma unroll
        for (int j = 0; j < 4; j++) {
            int i = tid + j * 256;
            int kk = i >> 6, n = i & 63;
            Bs[kk][n] = Wh[(size_t)(k0 + kk) * DKH + n];
        }
        __syncthreads();
#pragma unroll
        for (int kk = 0; kk < 16; kk++) {
            float a[4], b[4];
#pragma unroll
            for (int r = 0; r < 4; r++) a[r] = As[kk][ty * 4 + r];
            float4 bv = *(const float4*)&Bs[kk][tx * 4];
            b[0] = bv.x; b[1] = bv.y; b[2] = bv.z; b[3] = bv.w;
#pragma unroll
            for (int r = 0; r < 4; r++)
#pragma unroll
                for (int c = 0; c < 4; c++) acc[r][c] += a[r] * b[c];
        }
        __syncthreads();
    }

#pragma unroll
    for (int r = 0; r < 4; r++) {
        int m = m0 + ty * 4 + r;
#pragma unroll
        for (int c = 0; c < 4; c++) {
            int n = tx * 4 + c;   // within head
            C[(size_t)head * SQ * DKH + (size_t)m * DKH + n] =
                acc[r][c] + bias[n0 + n];
        }
    }
}

// ---------------------------------------------------------------------------
// Standard GEMM for output projection: out[s,n] = concat[s,:] @ Wo[:,n] + bo[n]
// ---------------------------------------------------------------------------
__global__ __launch_bounds__(256) void out_gemm_kernel(
    const float* __restrict__ A,      // [S, NHID]
    const float* __restrict__ B,      // [NHID, D] row-major
    const float* __restrict__ bias,   // [D]
    float* __restrict__ C)            // [S, D]
{
    __shared__ float As[16][65];
    __shared__ float Bs[16][64];

    const int tid = threadIdx.x;
    const int tx = tid & 15;
    const int ty = tid >> 4;
    const int m0 = blockIdx.y * 64;
    const int n0 = blockIdx.x * 64;

    float acc[4][4];
#pragma unroll
    for (int r = 0; r < 4; r++)
#pragma unroll
        for (int c = 0; c < 4; c++) acc[r][c] = 0.f;

    for (int k0 = 0; k0 < NHID; k0 += 16) {
#pragma unroll
        for (int j = 0; j < 4; j++) {
            int i = tid + j * 256;
            int m = i >> 4, kk = i & 15;
            As[kk][m] = A[(size_t)(m0 + m) * NHID + k0 + kk];
        }
#pragma unroll
        for (int j = 0; j < 4; j++) {
            int i = tid + j * 256;
            int kk = i >> 6, n = i & 63;
            Bs[kk][n] = B[(size_t)(k0 + kk) * DM + n0 + n];
        }
        __syncthreads();
#pragma unroll
        for (int kk = 0; kk < 16; kk++) {
            float a[4], b[4];
#pragma unroll
            for (int r = 0; r < 4; r++) a[r] = As[kk][ty * 4 + r];
            float4 bv = *(const float4*)&Bs[kk][tx * 4];
            b[0] = bv.x; b[1] = bv.y; b[2] = bv.z; b[3] = bv.w;
#pragma unroll
            for (int r = 0; r < 4; r++)
#pragma unroll
                for (int c = 0; c < 4; c++) acc[r][c] += a[r] * b[c];
        }
        __syncthreads();
    }

#pragma unroll
    for (int r = 0; r < 4; r++) {
        int m = m0 + ty * 4 + r;
#pragma unroll
        for (int c = 0; c < 4; c++) {
            int n = n0 + tx * 4 + c;
            C[(size_t)m * DM + n] = acc[r][c] + bias[n];
        }
    }
}

// ---------------------------------------------------------------------------
// Flash attention per (head, 64-row q tile). Online softmax, fp32.
// Dynamic smem layout: sQ[64][65], sKP[64][65] (K tile, reused for P), sV[64][65]
// ---------------------------------------------------------------------------
#define SMEM_ROW 65
#define ATTN_SMEM (3 * 64 * SMEM_ROW * 4)

__global__ __launch_bounds__(256) void attn_kernel(
    const float* __restrict__ q,   // [H, S, DK]
    const float* __restrict__ k,
    const float* __restrict__ v,
    float* __restrict__ concat)    // [S, H*DK]
{
    extern __shared__ float sm[];
    float (*sQ)[SMEM_ROW]  = (float (*)[SMEM_ROW])(sm);
    float (*sKP)[SMEM_ROW] = (float (*)[SMEM_ROW])(sm + 64 * SMEM_ROW);
    float (*sV)[SMEM_ROW]  = (float (*)[SMEM_ROW])(sm + 2 * 64 * SMEM_ROW);

    const int tid = threadIdx.x;
    const int tx = tid & 15;
    const int ty = tid >> 4;
    const int head = blockIdx.y;
    const int q0 = blockIdx.x * 64;

    const float* qb = q + ((size_t)head * SQ + q0) * DKH;
    const float* kb = k + (size_t)head * SQ * DKH;
    const float* vb = v + (size_t)head * SQ * DKH;

    // Load Q tile once, pre-scaled by 1/sqrt(DK) = 0.125
#pragma unroll
    for (int j = 0; j < 16; j++) {
        int i = tid + j * 256;         // 0..4095
        int r = i >> 6, cc = i & 63;
        sQ[r][cc] = qb[i] * 0.125f;
    }

    float mrow[4], lrow[4], acc[4][4];
#pragma unroll
    for (int r = 0; r < 4; r++) {
        mrow[r] = -1e30f;
        lrow[r] = 0.f;
#pragma unroll
        for (int c = 0; c < 4; c++) acc[r][c] = 0.f;
    }

    for (int t = 0; t < SQ / 64; t++) {
        __syncthreads();   // prior PV done (and covers sQ write ordering at t=0)
        const float* kt = kb + (size_t)t * 64 * DKH;
        const float* vt = vb + (size_t)t * 64 * DKH;
#pragma unroll
        for (int j = 0; j < 16; j++) {
            int i = tid + j * 256;
            int r = i >> 6, cc = i & 63;
            sKP[r][cc] = kt[i];
            sV[r][cc]  = vt[i];
        }
        __syncthreads();

        // scores s[r][c] = q_row . k_col (q pre-scaled)
        float s[4][4];
#pragma unroll
        for (int r = 0; r < 4; r++)
#pragma unroll
            for (int c = 0; c < 4; c++) s[r][c] = 0.f;
#pragma unroll 8
        for (int kk = 0; kk < 64; kk++) {
            float a[4], b[4];
#pragma unroll
            for (int r = 0; r < 4; r++) a[r] = sQ[ty * 4 + r][kk];
#pragma unroll
            for (int c = 0; c < 4; c++) b[c] = sKP[tx * 4 + c][kk];
#pragma unroll
            for (int r = 0; r < 4; r++)
#pragma unroll
                for (int c = 0; c < 4; c++) s[r][c] += a[r] * b[c];
        }

        // online softmax (row groups of 16 threads share a row set)
#pragma unroll
        for (int r = 0; r < 4; r++) {
            float tm = fmaxf(fmaxf(s[r][0], s[r][1]), fmaxf(s[r][2], s[r][3]));
#pragma unroll
            for (int mask = 8; mask >= 1; mask >>= 1)
                tm = fmaxf(tm, __shfl_xor_sync(0xffffffffu, tm, mask));
            float mnew = fmaxf(mrow[r], tm);
            float corr = __expf(mrow[r] - mnew);
            lrow[r] *= corr;
#pragma unroll
            for (int c = 0; c < 4; c++) acc[r][c] *= corr;
            float ps = 0.f;
#pragma unroll
            for (int c = 0; c < 4; c++) {
                s[r][c] = __expf(s[r][c] - mnew);
                ps += s[r][c];
            }
#pragma unroll
            for (int mask = 8; mask >= 1; mask >>= 1)
                ps += __shfl_xor_sync(0xffffffffu, ps, mask);
            lrow[r] += ps;
            mrow[r] = mnew;
        }

        __syncthreads();   // everyone done reading sKP as K
        // write P into sKP space
#pragma unroll
        for (int r = 0; r < 4; r++)
#pragma unroll
            for (int c = 0; c < 4; c++)
                sKP[ty * 4 + r][tx * 4 + c] = s[r][c];
        __syncthreads();

        // acc += P @ V
#pragma unroll 8
        for (int j = 0; j < 64; j++) {
            float a[4], b[4];
#pragma unroll
            for (int r = 0; r < 4; r++) a[r] = sKP[ty * 4 + r][j];
#pragma unroll
            for (int c = 0; c < 4; c++) b[c] = sV[j][tx * 4 + c];
#pragma unroll
            for (int r = 0; r < 4; r++)
#pragma unroll
                for (int c = 0; c < 4; c++) acc[r][c] += a[r] * b[c];
        }
    }

    // epilogue: normalize and write concat[s, head*DK + d]
#pragma unroll
    for (int r = 0; r < 4; r++) {
        int row = q0 + ty * 4 + r;
        float inv = 1.f / lrow[r];
#pragma unroll
        for (int c = 0; c < 4; c++) {
            int d = tx * 4 + c;
            concat[(size_t)row * NHID + head * DKH + d] = acc[r][c] * inv;
        }
    }
}

// ---------------------------------------------------------------------------
extern "C" void kernel_launch(void* const* d_in, const int* in_sizes, int n_in,
                              void* d_out, int out_size)
{
    const float* Q  = (const float*)d_in[0];
    const float* K  = (const float*)d_in[1];
    const float* V  = (const float*)d_in[2];
    const float* Wq = (const float*)d_in[3];
    const float* bq = (const float*)d_in[4];
    const float* Wk = (const float*)d_in[5];
    const float* bk = (const float*)d_in[6];
    const float* Wv = (const float*)d_in[7];
    const float* bv = (const float*)d_in[8];
    const float* Wo = (const float*)d_in[9];
    const float* bo = (const float*)d_in[10];
    float* out = (float*)d_out;

    float *gq, *gk, *gv, *gc;
    cudaGetSymbolAddress((void**)&gq, g_q);
    cudaGetSymbolAddress((void**)&gk, g_k);
    cudaGetSymbolAddress((void**)&gv, g_v);
    cudaGetSymbolAddress((void**)&gc, g_concat);

    cudaFuncSetAttribute(attn_kernel,
                         cudaFuncAttributeMaxDynamicSharedMemorySize, ATTN_SMEM);

    dim3 ggrid(NHID / 64, SQ / 64);   // (16, 32)
    proj_gemm_kernel<<<ggrid, 256>>>(Q, Wq, bq, gq);
    proj_gemm_kernel<<<ggrid, 256>>>(K, Wk, bk, gk);
    proj_gemm_kernel<<<ggrid, 256>>>(V, Wv, bv, gv);

    dim3 agrid(SQ / 64, NH);          // (32, 16)
    attn_kernel<<<agrid, 256, ATTN_SMEM>>>(gq, gk, gv, gc);

    dim3 ogrid(DM / 64, SQ / 64);     // (16, 32)
    out_gemm_kernel<<<ogrid, 256>>>(gc, Wo, bo, out);
}

// round 2
// speedup vs baseline: 2.1095x; 2.1095x over previous
#include <cuda_runtime.h>
#include <cuda_bf16.h>

#define SQ 2048
#define DM 1024
#define NH 16
#define DKH 64
#define NHID 1024

typedef unsigned int u32;
typedef unsigned short u16;

// Scratch planes (bf16 hi/lo split), __device__ globals per allocation rules.
__device__ __nv_bfloat16 g_qh[NH*SQ*DKH];
__device__ __nv_bfloat16 g_ql[NH*SQ*DKH];
__device__ __nv_bfloat16 g_kh[NH*SQ*DKH];
__device__ __nv_bfloat16 g_kl[NH*SQ*DKH];
__device__ __nv_bfloat16 g_vth[NH*DKH*SQ];   // V transposed: [H][DKH][S]
__device__ __nv_bfloat16 g_vtl[NH*DKH*SQ];
__device__ __nv_bfloat16 g_ch[SQ*NHID];
__device__ __nv_bfloat16 g_cl[SQ*NHID];

// ---------------------------------------------------------------------------
__device__ __forceinline__ void split1(float x, u16& h, u16& l) {
    __nv_bfloat16 hb = __float2bfloat16(x);
    h = __bfloat16_as_ushort(hb);
    l = __bfloat16_as_ushort(__float2bfloat16(x - __bfloat162float(hb)));
}
__device__ __forceinline__ void split_pack(float x0, float x1, u32& h, u32& l) {
    u16 h0,l0,h1,l1;
    split1(x0,h0,l0); split1(x1,h1,l1);
    h = ((u32)h1<<16)|h0; l = ((u32)l1<<16)|l0;
}

__device__ __forceinline__ void mma_bf16(float* c, const u32* a, const u32* b) {
    asm volatile(
      "mma.sync.aligned.m16n8k16.row.col.f32.bf16.bf16.f32 "
      "{%0,%1,%2,%3}, {%4,%5,%6,%7}, {%8,%9}, {%0,%1,%2,%3};\n"
      : "+f"(c[0]), "+f"(c[1]), "+f"(c[2]), "+f"(c[3])
      : "r"(a[0]), "r"(a[1]), "r"(a[2]), "r"(a[3]), "r"(b[0]), "r"(b[1]));
}
// 3-term split product: hi*hi + hi*lo + lo*hi (lo*lo dropped, ~2^-16)
__device__ __forceinline__ void mma3(float* c, const u32* ah, const u32* al,
                                     const u32* bh, const u32* bl) {
    mma_bf16(c, ah, bh);
    mma_bf16(c, ah, bl);
    mma_bf16(c, al, bh);
}

// ---------------------------------------------------------------------------
// Projection GEMM: C[h,s,n] = A[s,:] @ W[h,:,n] + bias[h,n]
// Block: 128(M) x 64(N=one head), BK=32. 8 warps, warp tile 32x32.
// Output written as bf16 hi/lo planes; transposed=1 writes [H][DKH][S] (for V).
// ---------------------------------------------------------------------------
__global__ __launch_bounds__(256) void proj_kernel(
    const float* __restrict__ A, const float* __restrict__ W,
    const float* __restrict__ bias,
    __nv_bfloat16* __restrict__ outH, __nv_bfloat16* __restrict__ outL,
    int transposed)
{
    __shared__ __align__(16) u16 sAh[128*40], sAl[128*40];
    __shared__ __align__(16) u16 sBh[64*40],  sBl[64*40];
    u32* pAh=(u32*)sAh; u32* pAl=(u32*)sAl;
    u32* pBh=(u32*)sBh; u32* pBl=(u32*)sBl;

    const int tid = threadIdx.x;
    const int lane = tid & 31, wid = tid >> 5;
    const int g = lane >> 2, t4 = lane & 3;
    const int wm = wid >> 1, wn = wid & 1;
    const int head = blockIdx.x;
    const int m0 = blockIdx.y * 128;
    const float* Wh = W + (size_t)head * DM * DKH;

    float acc[2][4][4];
#pragma unroll
    for (int i=0;i<2;i++)
#pragma unroll
      for (int j=0;j<4;j++)
#pragma unroll
        for (int e=0;e<4;e++) acc[i][j][e]=0.f;

    for (int k0 = 0; k0 < DM; k0 += 32) {
        // stage A (fp32 -> split planes), 128x32
#pragma unroll
        for (int j=0;j<4;j++){
            int i = tid + j*256;              // 0..1023 float4 units
            int r = i>>3, c4 = i&7;
            float4 av = *(const float4*)(A + (size_t)(m0+r)*DM + k0 + c4*4);
            u32 h0,l0,h1,l1;
            split_pack(av.x,av.y,h0,l0); split_pack(av.z,av.w,h1,l1);
            int w = r*20 + c4*2;
            pAh[w]=h0; pAh[w+1]=h1; pAl[w]=l0; pAl[w+1]=l1;
        }
        // stage B: Wh tile 32(k)x64(n), transpose to [n][k] planes
#pragma unroll
        for (int j=0;j<2;j++){
            int i = tid + j*256;              // 0..511 float4 units
            int kk = i>>4, c4 = i&15;
            float4 wv = *(const float4*)(Wh + (size_t)(k0+kk)*DKH + c4*4);
            int n = c4*4;
            u16 h,l;
            split1(wv.x,h,l); sBh[(n+0)*40+kk]=h; sBl[(n+0)*40+kk]=l;
            split1(wv.y,h,l); sBh[(n+1)*40+kk]=h; sBl[(n+1)*40+kk]=l;
            split1(wv.z,h,l); sBh[(n+2)*40+kk]=h; sBl[(n+2)*40+kk]=l;
            split1(wv.w,h,l); sBh[(n+3)*40+kk]=h; sBl[(n+3)*40+kk]=l;
        }
        __syncthreads();

#pragma unroll
        for (int ks=0; ks<2; ks++){
            u32 ah[2][4], al[2][4];
#pragma unroll
            for (int i=0;i<2;i++){
                int row = wm*32 + i*16;
                int b0 = (row+g)*20 + ks*8 + t4;
                int b1 = (row+g+8)*20 + ks*8 + t4;
                ah[i][0]=pAh[b0]; ah[i][1]=pAh[b1]; ah[i][2]=pAh[b0+4]; ah[i][3]=pAh[b1+4];
                al[i][0]=pAl[b0]; al[i][1]=pAl[b1]; al[i][2]=pAl[b0+4]; al[i][3]=pAl[b1+4];
            }
#pragma unroll
            for (int j=0;j<4;j++){
                int n = wn*32 + j*8 + g;
                u32 bh[2], bl[2];
                bh[0]=pBh[n*20+ks*8+t4]; bh[1]=pBh[n*20+ks*8+4+t4];
                bl[0]=pBl[n*20+ks*8+t4]; bl[1]=pBl[n*20+ks*8+4+t4];
#pragma unroll
                for (int i=0;i<2;i++) mma3(acc[i][j], ah[i], al[i], bh, bl);
            }
        }
        __syncthreads();
    }

    // epilogue: +bias, split to planes
#pragma unroll
    for (int i=0;i<2;i++){
#pragma unroll
        for (int j=0;j<4;j++){
            int r0 = m0 + wm*32 + i*16 + g;
            int r1 = r0 + 8;
            int col = wn*32 + j*8 + t4*2;
            float b0f = bias[head*DKH + col];
            float b1f = bias[head*DKH + col + 1];
            float v0 = acc[i][j][0] + b0f;
            float v1 = acc[i][j][1] + b1f;
            float v2 = acc[i][j][2] + b0f;
            float v3 = acc[i][j][3] + b1f;
            if (!transposed) {
                u32 h,l;
                split_pack(v0,v1,h,l);
                ((u32*)outH)[(head*SQ + r0)*32 + (col>>1)] = h;
                ((u32*)outL)[(head*SQ + r0)*32 + (col>>1)] = l;
                split_pack(v2,v3,h,l);
                ((u32*)outH)[(head*SQ + r1)*32 + (col>>1)] = h;
                ((u32*)outL)[(head*SQ + r1)*32 + (col>>1)] = l;
            } else {
                u16 h,l;
                u16* oH = (u16*)outH; u16* oL = (u16*)outL;
                split1(v0,h,l); oH[(head*DKH+col  )*SQ + r0]=h; oL[(head*DKH+col  )*SQ + r0]=l;
                split1(v1,h,l); oH[(head*DKH+col+1)*SQ + r0]=h; oL[(head*DKH+col+1)*SQ + r0]=l;
                split1(v2,h,l); oH[(head*DKH+col  )*SQ + r1]=h; oL[(head*DKH+col  )*SQ + r1]=l;
                split1(v3,h,l); oH[(head*DKH+col+1)*SQ + r1]=h; oL[(head*DKH+col+1)*SQ + r1]=l;
            }
        }
    }
}

// ---------------------------------------------------------------------------
// Output projection: out[s,n] = concat[s,:] @ Wo[:,n] + bo[n]
// A comes pre-split (concat planes). Same tiling as proj_kernel.
// ---------------------------------------------------------------------------
__global__ __launch_bounds__(256) void out_kernel(
    const u32* __restrict__ Ah, const u32* __restrict__ Al,
    const float* __restrict__ B, const float* __restrict__ bias,
    float* __restrict__ C)
{
    __shared__ __align__(16) u16 sAh[128*40], sAl[128*40];
    __shared__ __align__(16) u16 sBh[64*40],  sBl[64*40];
    u32* pAh=(u32*)sAh; u32* pAl=(u32*)sAl;
    u32* pBh=(u32*)sBh; u32* pBl=(u32*)sBl;

    const int tid = threadIdx.x;
    const int lane = tid & 31, wid = tid >> 5;
    const int g = lane >> 2, t4 = lane & 3;
    const int wm = wid >> 1, wn = wid & 1;
    const int n0 = blockIdx.x * 64;
    const int m0 = blockIdx.y * 128;

    float acc[2][4][4];
#pragma unroll
    for (int i=0;i<2;i++)
#pragma unroll
      for (int j=0;j<4;j++)
#pragma unroll
        for (int e=0;e<4;e++) acc[i][j][e]=0.f;

    for (int k0 = 0; k0 < NHID; k0 += 32) {
        // stage A from planes (already bf16 split)
#pragma unroll
        for (int j=0;j<8;j++){
            int i = tid + j*256;              // 0..2047 words
            int r = i>>4, cw = i&15;
            int gw = (m0+r)*512 + (k0>>1) + cw;
            pAh[r*20+cw] = Ah[gw];
            pAl[r*20+cw] = Al[gw];
        }
        // stage B: Wo tile 32x64, transpose+split
#pragma unroll
        for (int j=0;j<2;j++){
            int i = tid + j*256;
            int kk = i>>4, c4 = i&15;
            float4 wv = *(const float4*)(B + (size_t)(k0+kk)*DM + n0 + c4*4);
            int n = c4*4;
            u16 h,l;
            split1(wv.x,h,l); sBh[(n+0)*40+kk]=h; sBl[(n+0)*40+kk]=l;
            split1(wv.y,h,l); sBh[(n+1)*40+kk]=h; sBl[(n+1)*40+kk]=l;
            split1(wv.z,h,l); sBh[(n+2)*40+kk]=h; sBl[(n+2)*40+kk]=l;
            split1(wv.w,h,l); sBh[(n+3)*40+kk]=h; sBl[(n+3)*40+kk]=l;
        }
        __syncthreads();

#pragma unroll
        for (int ks=0; ks<2; ks++){
            u32 ah[2][4], al[2][4];
#pragma unroll
            for (int i=0;i<2;i++){
                int row = wm*32 + i*16;
                int b0 = (row+g)*20 + ks*8 + t4;
                int b1 = (row+g+8)*20 + ks*8 + t4;
                ah[i][0]=pAh[b0]; ah[i][1]=pAh[b1]; ah[i][2]=pAh[b0+4]; ah[i][3]=pAh[b1+4];
                al[i][0]=pAl[b0]; al[i][1]=pAl[b1]; al[i][2]=pAl[b0+4]; al[i][3]=pAl[b1+4];
            }
#pragma unroll
            for (int j=0;j<4;j++){
                int n = wn*32 + j*8 + g;
                u32 bh[2], bl[2];
                bh[0]=pBh[n*20+ks*8+t4]; bh[1]=pBh[n*20+ks*8+4+t4];
                bl[0]=pBl[n*20+ks*8+t4]; bl[1]=pBl[n*20+ks*8+4+t4];
#pragma unroll
                for (int i=0;i<2;i++) mma3(acc[i][j], ah[i], al[i], bh, bl);
            }
        }
        __syncthreads();
    }

#pragma unroll
    for (int i=0;i<2;i++){
#pragma unroll
        for (int j=0;j<4;j++){
            int r0 = m0 + wm*32 + i*16 + g;
            int r1 = r0 + 8;
            int col = n0 + wn*32 + j*8 + t4*2;
            C[(size_t)r0*DM + col    ] = acc[i][j][0] + bias[col];
            C[(size_t)r0*DM + col + 1] = acc[i][j][1] + bias[col+1];
            C[(size_t)r1*DM + col    ] = acc[i][j][2] + bias[col];
            C[(size_t)r1*DM + col + 1] = acc[i][j][3] + bias[col+1];
        }
    }
}

// ---------------------------------------------------------------------------
// Flash attention, MMA version.
// Block: 128 q rows x 1 head; 8 warps, each 16 rows x full 64-key width.
// Q fragments preloaded to registers for all key tiles. Score C-frags
// reinterpret directly as P A-frags for PV (no smem round-trip).
// ---------------------------------------------------------------------------
#define ASTRIDE 36   // 72 halves row stride (64 + 8 pad), in 32-bit words
#define ATTN_SMEM ((128*ASTRIDE*2 + 64*ASTRIDE*4) * 4)

__global__ __launch_bounds__(256) void attn_kernel(
    const u32* __restrict__ Qh, const u32* __restrict__ Ql,
    const u32* __restrict__ Kh, const u32* __restrict__ Kl,
    const u32* __restrict__ Vh, const u32* __restrict__ Vl,
    __nv_bfloat16* __restrict__ Ch, __nv_bfloat16* __restrict__ Cl)
{
    extern __shared__ u32 sm[];
    u32* sQh = sm;
    u32* sQl = sQh + 128*ASTRIDE;
    u32* sKh = sQl + 128*ASTRIDE;
    u32* sKl = sKh + 64*ASTRIDE;
    u32* sVh = sKl + 64*ASTRIDE;
    u32* sVl = sVh + 64*ASTRIDE;

    const int tid = threadIdx.x, lane = tid&31, wid = tid>>5;
    const int g = lane>>2, t4 = lane&3;
    const int h = blockIdx.y, q0 = blockIdx.x*128;

    // stage Q planes (128 x 64 halves = 32 words/row)
#pragma unroll
    for (int j=0;j<16;j++){
        int i = tid + j*256;
        int r = i>>5, cw = i&31;
        int gw = (h*SQ + q0 + r)*32 + cw;
        sQh[r*ASTRIDE+cw] = Qh[gw];
        sQl[r*ASTRIDE+cw] = Ql[gw];
    }
    __syncthreads();

    // preload Q fragments for all 4 k-steps (d=64)
    u32 qfh[4][4], qfl[4][4];
    {
        int row = wid*16;
#pragma unroll
        for (int ks=0;ks<4;ks++){
            int b0 = (row+g)*ASTRIDE + ks*8 + t4;
            int b1 = (row+g+8)*ASTRIDE + ks*8 + t4;
            qfh[ks][0]=sQh[b0]; qfh[ks][1]=sQh[b1]; qfh[ks][2]=sQh[b0+4]; qfh[ks][3]=sQh[b1+4];
            qfl[ks][0]=sQl[b0]; qfl[ks][1]=sQl[b1]; qfl[ks][2]=sQl[b0+4]; qfl[ks][3]=sQl[b1+4];
        }
    }

    float oacc[8][4];
#pragma unroll
    for (int j=0;j<8;j++)
#pragma unroll
        for (int e=0;e<4;e++) oacc[j][e]=0.f;
    float m0r=-1e30f, m1r=-1e30f, l0r=0.f, l1r=0.f;

    for (int t=0; t<SQ/64; t++){
        if (t) __syncthreads();
        // stage K tile [64 keys][64 d] and V^T tile [64 d][64 keys]
#pragma unroll
        for (int j=0;j<8;j++){
            int i = tid + j*256;
            int r = i>>5, cw = i&31;
            int gk = (h*SQ + t*64 + r)*32 + cw;
            sKh[r*ASTRIDE+cw] = Kh[gk];
            sKl[r*ASTRIDE+cw] = Kl[gk];
            int gv = (h*DKH + r)*1024 + t*32 + cw;
            sVh[r*ASTRIDE+cw] = Vh[gv];
            sVl[r*ASTRIDE+cw] = Vl[gv];
        }
        __syncthreads();

        // scores: 16 rows x 64 keys per warp
        float sc[8][4];
#pragma unroll
        for (int j=0;j<8;j++)
#pragma unroll
            for (int e=0;e<4;e++) sc[j][e]=0.f;
#pragma unroll
        for (int ks=0;ks<4;ks++){
#pragma unroll
            for (int j=0;j<8;j++){
                int n=(j*8+g)*ASTRIDE + ks*8 + t4;
                u32 bh[2], bl[2];
                bh[0]=sKh[n]; bh[1]=sKh[n+4];
                bl[0]=sKl[n]; bl[1]=sKl[n+4];
                mma3(sc[j], qfh[ks], qfl[ks], bh, bl);
            }
        }

        // scale + online softmax (rows g and g+8; quad-local reduce)
        float tm0=-1e30f, tm1=-1e30f;
#pragma unroll
        for (int j=0;j<8;j++){
            sc[j][0]*=0.125f; sc[j][1]*=0.125f; sc[j][2]*=0.125f; sc[j][3]*=0.125f;
            tm0 = fmaxf(tm0, fmaxf(sc[j][0], sc[j][1]));
            tm1 = fmaxf(tm1, fmaxf(sc[j][2], sc[j][3]));
        }
        tm0 = fmaxf(tm0, __shfl_xor_sync(0xffffffffu, tm0, 1));
        tm0 = fmaxf(tm0, __shfl_xor_sync(0xffffffffu, tm0, 2));
        tm1 = fmaxf(tm1, __shfl_xor_sync(0xffffffffu, tm1, 1));
        tm1 = fmaxf(tm1, __shfl_xor_sync(0xffffffffu, tm1, 2));
        float mn0 = fmaxf(m0r, tm0), mn1 = fmaxf(m1r, tm1);
        float c0 = __expf(m0r - mn0), c1 = __expf(m1r - mn1);
        float rs0=0.f, rs1=0.f;
#pragma unroll
        for (int j=0;j<8;j++){
            sc[j][0]=__expf(sc[j][0]-mn0); sc[j][1]=__expf(sc[j][1]-mn0);
            sc[j][2]=__expf(sc[j][2]-mn1); sc[j][3]=__expf(sc[j][3]-mn1);
            rs0 += sc[j][0]+sc[j][1]; rs1 += sc[j][2]+sc[j][3];
        }
        rs0 += __shfl_xor_sync(0xffffffffu, rs0, 1);
        rs0 += __shfl_xor_sync(0xffffffffu, rs0, 2);
        rs1 += __shfl_xor_sync(0xffffffffu, rs1, 1);
        rs1 += __shfl_xor_sync(0xffffffffu, rs1, 2);
        l0r = l0r*c0 + rs0; l1r = l1r*c1 + rs1;
        m0r = mn0; m1r = mn1;
#pragma unroll
        for (int j=0;j<8;j++){
            oacc[j][0]*=c0; oacc[j][1]*=c0; oacc[j][2]*=c1; oacc[j][3]*=c1;
        }

        // PV: P frags built in-register from score frags
#pragma unroll
        for (int s=0;s<4;s++){
            u32 ph[4], pl[4];
            split_pack(sc[2*s  ][0], sc[2*s  ][1], ph[0], pl[0]);
            split_pack(sc[2*s  ][2], sc[2*s  ][3], ph[1], pl[1]);
            split_pack(sc[2*s+1][0], sc[2*s+1][1], ph[2], pl[2]);
            split_pack(sc[2*s+1][2], sc[2*s+1][3], ph[3], pl[3]);
#pragma unroll
            for (int j=0;j<8;j++){
                int n=(j*8+g)*ASTRIDE + s*8 + t4;
                u32 bh[2], bl[2];
                bh[0]=sVh[n]; bh[1]=sVh[n+4];
                bl[0]=sVl[n]; bl[1]=sVl[n+4];
                mma3(oacc[j], ph, pl, bh, bl);
            }
        }
    }

    // epilogue: normalize, split, write concat planes
    float inv0 = 1.f/l0r, inv1 = 1.f/l1r;
    int r0 = q0 + wid*16 + g, r1 = r0+8;
#pragma unroll
    for (int j=0;j<8;j++){
        int col = h*DKH + j*8 + t4*2;
        u32 hh, ll;
        split_pack(oacc[j][0]*inv0, oacc[j][1]*inv0, hh, ll);
        ((u32*)Ch)[(r0*NHID + col)>>1] = hh;
        ((u32*)Cl)[(r0*NHID + col)>>1] = ll;
        split_pack(oacc[j][2]*inv1, oacc[j][3]*inv1, hh, ll);
        ((u32*)Ch)[(r1*NHID + col)>>1] = hh;
        ((u32*)Cl)[(r1*NHID + col)>>1] = ll;
    }
}

// ---------------------------------------------------------------------------
extern "C" void kernel_launch(void* const* d_in, const int* in_sizes, int n_in,
                              void* d_out, int out_size)
{
    const float* Q  = (const float*)d_in[0];
    const float* K  = (const float*)d_in[1];
    const float* V  = (const float*)d_in[2];
    const float* Wq = (const float*)d_in[3];
    const float* bq = (const float*)d_in[4];
    const float* Wk = (const float*)d_in[5];
    const float* bk = (const float*)d_in[6];
    const float* Wv = (const float*)d_in[7];
    const float* bv = (const float*)d_in[8];
    const float* Wo = (const float*)d_in[9];
    const float* bo = (const float*)d_in[10];
    float* out = (float*)d_out;

    __nv_bfloat16 *qh,*ql,*kh,*kl,*vth,*vtl,*ch,*cl;
    cudaGetSymbolAddress((void**)&qh,  g_qh);
    cudaGetSymbolAddress((void**)&ql,  g_ql);
    cudaGetSymbolAddress((void**)&kh,  g_kh);
    cudaGetSymbolAddress((void**)&kl,  g_kl);
    cudaGetSymbolAddress((void**)&vth, g_vth);
    cudaGetSymbolAddress((void**)&vtl, g_vtl);
    cudaGetSymbolAddress((void**)&ch,  g_ch);
    cudaGetSymbolAddress((void**)&cl,  g_cl);

    cudaFuncSetAttribute(attn_kernel,
                         cudaFuncAttributeMaxDynamicSharedMemorySize, ATTN_SMEM);

    dim3 pg(NHID/64, SQ/128);     // (16, 16)
    proj_kernel<<<pg, 256>>>(Q, Wq, bq, qh,  ql,  0);
    proj_kernel<<<pg, 256>>>(K, Wk, bk, kh,  kl,  0);
    proj_kernel<<<pg, 256>>>(V, Wv, bv, vth, vtl, 1);

    dim3 ag(SQ/128, NH);          // (16, 16)
    attn_kernel<<<ag, 256, ATTN_SMEM>>>((u32*)qh,(u32*)ql,(u32*)kh,(u32*)kl,
                                        (u32*)vth,(u32*)vtl, ch, cl);

    dim3 og(DM/64, SQ/128);       // (16, 16)
    out_kernel<<<og, 256>>>((u32*)ch,(u32*)cl, Wo, bo, out);
}

// round 5
// speedup vs baseline: 2.3730x; 1.1249x over previous
#include <cuda_runtime.h>
#include <cuda_bf16.h>

#define SQ 2048
#define DM 1024
#define NH 16
#define DKH 64
#define NHID 1024

typedef unsigned int u32;
typedef unsigned short u16;

// Scratch planes (bf16 hi/lo split)
__device__ __nv_bfloat16 g_qh[NH*SQ*DKH];
__device__ __nv_bfloat16 g_ql[NH*SQ*DKH];
__device__ __nv_bfloat16 g_kh[NH*SQ*DKH];
__device__ __nv_bfloat16 g_kl[NH*SQ*DKH];
__device__ __nv_bfloat16 g_vth[NH*DKH*SQ];   // V transposed: [H][DKH][S]
__device__ __nv_bfloat16 g_vtl[NH*DKH*SQ];
__device__ __nv_bfloat16 g_ch[SQ*NHID];
__device__ __nv_bfloat16 g_cl[SQ*NHID];

// ---------------------------------------------------------------------------
__device__ __forceinline__ void split1(float x, u16& h, u16& l) {
    __nv_bfloat16 hb = __float2bfloat16(x);
    h = __bfloat16_as_ushort(hb);
    l = __bfloat16_as_ushort(__float2bfloat16(x - __bfloat162float(hb)));
}
__device__ __forceinline__ void split_pack(float x0, float x1, u32& h, u32& l) {
    u16 h0,l0,h1,l1;
    split1(x0,h0,l0); split1(x1,h1,l1);
    h = ((u32)h1<<16)|h0; l = ((u32)l1<<16)|l0;
}

__device__ __forceinline__ void mma_bf16(float* c, const u32* a, const u32* b) {
    asm volatile(
      "mma.sync.aligned.m16n8k16.row.col.f32.bf16.bf16.f32 "
      "{%0,%1,%2,%3}, {%4,%5,%6,%7}, {%8,%9}, {%0,%1,%2,%3};\n"
      : "+f"(c[0]), "+f"(c[1]), "+f"(c[2]), "+f"(c[3])
      : "r"(a[0]), "r"(a[1]), "r"(a[2]), "r"(a[3]), "r"(b[0]), "r"(b[1]));
}
__device__ __forceinline__ void mma3(float* c, const u32* ah, const u32* al,
                                     const u32* bh, const u32* bl) {
    mma_bf16(c, ah, bh);
    mma_bf16(c, ah, bl);
    mma_bf16(c, al, bh);
}

// cp.async helpers
__device__ __forceinline__ void cp16(u32 dst_smem, const void* src) {
    asm volatile("cp.async.cg.shared.global [%0], [%1], 16;\n"
                 :: "r"(dst_smem), "l"(src));
}
__device__ __forceinline__ void cp_commit() {
    asm volatile("cp.async.commit_group;\n");
}
template<int N> __device__ __forceinline__ void cp_wait() {
    asm volatile("cp.async.wait_group %0;\n" :: "n"(N));
}

// ---------------------------------------------------------------------------
// Fused projection GEMM (Q, K, V in one launch; blockIdx.z selects which).
// Block: 128(M) x 64(N=one head), BK=32, 8 warps, warp tile 32x32.
// Register-prefetch double buffering on global loads.
// Q outputs pre-scaled by 0.125; V written transposed [H][DKH][S].
// ---------------------------------------------------------------------------
__global__ __launch_bounds__(256) void proj_kernel(
    const float* __restrict__ Qi, const float* __restrict__ Ki,
    const float* __restrict__ Vi,
    const float* __restrict__ Wq, const float* __restrict__ Wk,
    const float* __restrict__ Wv,
    const float* __restrict__ bq, const float* __restrict__ bk,
    const float* __restrict__ bv,
    __nv_bfloat16* __restrict__ oqh, __nv_bfloat16* __restrict__ oql,
    __nv_bfloat16* __restrict__ okh, __nv_bfloat16* __restrict__ okl,
    __nv_bfloat16* __restrict__ ovh, __nv_bfloat16* __restrict__ ovl)
{
    const int which = blockIdx.z;
    const float* A    = (which==0) ? Qi : (which==1) ? Ki : Vi;
    const float* W    = (which==0) ? Wq : (which==1) ? Wk : Wv;
    const float* bias = (which==0) ? bq : (which==1) ? bk : bv;
    __nv_bfloat16* outH = (which==0) ? oqh : (which==1) ? okh : ovh;
    __nv_bfloat16* outL = (which==0) ? oql : (which==1) ? okl : ovl;
    const int transposed = (which==2);
    const float osc = (which==0) ? 0.125f : 1.f;

    __shared__ __align__(16) u16 sAh[128*40], sAl[128*40];
    __shared__ __align__(16) u16 sBh[64*40],  sBl[64*40];
    u32* pAh=(u32*)sAh; u32* pAl=(u32*)sAl;
    u32* pBh=(u32*)sBh; u32* pBl=(u32*)sBl;

    const int tid = threadIdx.x;
    const int lane = tid & 31, wid = tid >> 5;
    const int g = lane >> 2, t4 = lane & 3;
    const int wm = wid >> 1, wn = wid & 1;
    const int head = blockIdx.x;
    const int m0 = blockIdx.y * 128;
    const float* Wh = W + (size_t)head * DM * DKH;

    float acc[2][4][4];
#pragma unroll
    for (int i=0;i<2;i++)
#pragma unroll
      for (int j=0;j<4;j++)
#pragma unroll
        for (int e=0;e<4;e++) acc[i][j][e]=0.f;

    float4 aR[4], bR[2];
    // initial global loads (k0 = 0)
#pragma unroll
    for (int j=0;j<4;j++){
        int i = tid + j*256;
        int r = i>>3, c4 = i&7;
        aR[j] = *(const float4*)(A + (size_t)(m0+r)*DM + c4*4);
    }
#pragma unroll
    for (int j=0;j<2;j++){
        int i = tid + j*256;
        int kk = i>>4, c4 = i&15;
        bR[j] = *(const float4*)(Wh + (size_t)kk*DKH + c4*4);
    }

    for (int k0 = 0; k0 < DM; k0 += 32) {
        __syncthreads();   // previous compute finished reading smem
        // stage from regs (split to planes)
#pragma unroll
        for (int j=0;j<4;j++){
            int i = tid + j*256;
            int r = i>>3, c4 = i&7;
            u32 h0,l0,h1,l1;
            split_pack(aR[j].x,aR[j].y,h0,l0);
            split_pack(aR[j].z,aR[j].w,h1,l1);
            int w = r*20 + c4*2;
            pAh[w]=h0; pAh[w+1]=h1; pAl[w]=l0; pAl[w+1]=l1;
        }
#pragma unroll
        for (int j=0;j<2;j++){
            int i = tid + j*256;
            int kk = i>>4, c4 = i&15;
            int n = c4*4;
            u16 h,l;
            split1(bR[j].x,h,l); sBh[(n+0)*40+kk]=h; sBl[(n+0)*40+kk]=l;
            split1(bR[j].y,h,l); sBh[(n+1)*40+kk]=h; sBl[(n+1)*40+kk]=l;
            split1(bR[j].z,h,l); sBh[(n+2)*40+kk]=h; sBl[(n+2)*40+kk]=l;
            split1(bR[j].w,h,l); sBh[(n+3)*40+kk]=h; sBl[(n+3)*40+kk]=l;
        }
        __syncthreads();

        // prefetch next tile's globals (hidden behind MMAs)
        if (k0 + 32 < DM) {
#pragma unroll
            for (int j=0;j<4;j++){
                int i = tid + j*256;
                int r = i>>3, c4 = i&7;
                aR[j] = *(const float4*)(A + (size_t)(m0+r)*DM + (k0+32) + c4*4);
            }
#pragma unroll
            for (int j=0;j<2;j++){
                int i = tid + j*256;
                int kk = i>>4, c4 = i&15;
                bR[j] = *(const float4*)(Wh + (size_t)(k0+32+kk)*DKH + c4*4);
            }
        }

#pragma unroll
        for (int ks=0; ks<2; ks++){
            u32 ah[2][4], al[2][4];
#pragma unroll
            for (int i=0;i<2;i++){
                int row = wm*32 + i*16;
                int b0 = (row+g)*20 + ks*8 + t4;
                int b1 = (row+g+8)*20 + ks*8 + t4;
                ah[i][0]=pAh[b0]; ah[i][1]=pAh[b1]; ah[i][2]=pAh[b0+4]; ah[i][3]=pAh[b1+4];
                al[i][0]=pAl[b0]; al[i][1]=pAl[b1]; al[i][2]=pAl[b0+4]; al[i][3]=pAl[b1+4];
            }
#pragma unroll
            for (int j=0;j<4;j++){
                int n = wn*32 + j*8 + g;
                u32 bh[2], bl[2];
                bh[0]=pBh[n*20+ks*8+t4]; bh[1]=pBh[n*20+ks*8+4+t4];
                bl[0]=pBl[n*20+ks*8+t4]; bl[1]=pBl[n*20+ks*8+4+t4];
#pragma unroll
                for (int i=0;i<2;i++) mma3(acc[i][j], ah[i], al[i], bh, bl);
            }
        }
    }

    // epilogue
#pragma unroll
    for (int i=0;i<2;i++){
#pragma unroll
        for (int j=0;j<4;j++){
            int r0 = m0 + wm*32 + i*16 + g;
            int r1 = r0 + 8;
            int col = wn*32 + j*8 + t4*2;
            float b0f = bias[head*DKH + col];
            float b1f = bias[head*DKH + col + 1];
            float v0 = (acc[i][j][0] + b0f) * osc;
            float v1 = (acc[i][j][1] + b1f) * osc;
            float v2 = (acc[i][j][2] + b0f) * osc;
            float v3 = (acc[i][j][3] + b1f) * osc;
            if (!transposed) {
                u32 h,l;
                split_pack(v0,v1,h,l);
                ((u32*)outH)[(head*SQ + r0)*32 + (col>>1)] = h;
                ((u32*)outL)[(head*SQ + r0)*32 + (col>>1)] = l;
                split_pack(v2,v3,h,l);
                ((u32*)outH)[(head*SQ + r1)*32 + (col>>1)] = h;
                ((u32*)outL)[(head*SQ + r1)*32 + (col>>1)] = l;
            } else {
                u16 h,l;
                u16* oH = (u16*)outH; u16* oL = (u16*)outL;
                split1(v0,h,l); oH[(head*DKH+col  )*SQ + r0]=h; oL[(head*DKH+col  )*SQ + r0]=l;
                split1(v1,h,l); oH[(head*DKH+col+1)*SQ + r0]=h; oL[(head*DKH+col+1)*SQ + r0]=l;
                split1(v2,h,l); oH[(head*DKH+col  )*SQ + r1]=h; oL[(head*DKH+col  )*SQ + r1]=l;
                split1(v3,h,l); oH[(head*DKH+col+1)*SQ + r1]=h; oL[(head*DKH+col+1)*SQ + r1]=l;
            }
        }
    }
}

// ---------------------------------------------------------------------------
// Output projection with register-prefetch double buffering.
// ---------------------------------------------------------------------------
__global__ __launch_bounds__(256) void out_kernel(
    const u32* __restrict__ Ah, const u32* __restrict__ Al,
    const float* __restrict__ B, const float* __restrict__ bias,
    float* __restrict__ C)
{
    __shared__ __align__(16) u16 sAh[128*40], sAl[128*40];
    __shared__ __align__(16) u16 sBh[64*40],  sBl[64*40];
    u32* pAh=(u32*)sAh; u32* pAl=(u32*)sAl;
    u32* pBh=(u32*)sBh; u32* pBl=(u32*)sBl;

    const int tid = threadIdx.x;
    const int lane = tid & 31, wid = tid >> 5;
    const int g = lane >> 2, t4 = lane & 3;
    const int wm = wid >> 1, wn = wid & 1;
    const int n0 = blockIdx.x * 64;
    const int m0 = blockIdx.y * 128;

    float acc[2][4][4];
#pragma unroll
    for (int i=0;i<2;i++)
#pragma unroll
      for (int j=0;j<4;j++)
#pragma unroll
        for (int e=0;e<4;e++) acc[i][j][e]=0.f;

    u32 aRh[8], aRl[8];
    float4 bR[2];
#pragma unroll
    for (int j=0;j<8;j++){
        int i = tid + j*256;
        int r = i>>4, cw = i&15;
        int gw = (m0+r)*512 + cw;
        aRh[j] = Ah[gw]; aRl[j] = Al[gw];
    }
#pragma unroll
    for (int j=0;j<2;j++){
        int i = tid + j*256;
        int kk = i>>4, c4 = i&15;
        bR[j] = *(const float4*)(B + (size_t)kk*DM + n0 + c4*4);
    }

    for (int k0 = 0; k0 < NHID; k0 += 32) {
        __syncthreads();
#pragma unroll
        for (int j=0;j<8;j++){
            int i = tid + j*256;
            int r = i>>4, cw = i&15;
            pAh[r*20+cw] = aRh[j];
            pAl[r*20+cw] = aRl[j];
        }
#pragma unroll
        for (int j=0;j<2;j++){
            int i = tid + j*256;
            int kk = i>>4, c4 = i&15;
            int n = c4*4;
            u16 h,l;
            split1(bR[j].x,h,l); sBh[(n+0)*40+kk]=h; sBl[(n+0)*40+kk]=l;
            split1(bR[j].y,h,l); sBh[(n+1)*40+kk]=h; sBl[(n+1)*40+kk]=l;
            split1(bR[j].z,h,l); sBh[(n+2)*40+kk]=h; sBl[(n+2)*40+kk]=l;
            split1(bR[j].w,h,l); sBh[(n+3)*40+kk]=h; sBl[(n+3)*40+kk]=l;
        }
        __syncthreads();

        if (k0 + 32 < NHID) {
#pragma unroll
            for (int j=0;j<8;j++){
                int i = tid + j*256;
                int r = i>>4, cw = i&15;
                int gw = (m0+r)*512 + ((k0+32)>>1) + cw;
                aRh[j] = Ah[gw]; aRl[j] = Al[gw];
            }
#pragma unroll
            for (int j=0;j<2;j++){
                int i = tid + j*256;
                int kk = i>>4, c4 = i&15;
                bR[j] = *(const float4*)(B + (size_t)(k0+32+kk)*DM + n0 + c4*4);
            }
        }

#pragma unroll
        for (int ks=0; ks<2; ks++){
            u32 ah[2][4], al[2][4];
#pragma unroll
            for (int i=0;i<2;i++){
                int row = wm*32 + i*16;
                int b0 = (row+g)*20 + ks*8 + t4;
                int b1 = (row+g+8)*20 + ks*8 + t4;
                ah[i][0]=pAh[b0]; ah[i][1]=pAh[b1]; ah[i][2]=pAh[b0+4]; ah[i][3]=pAh[b1+4];
                al[i][0]=pAl[b0]; al[i][1]=pAl[b1]; al[i][2]=pAl[b0+4]; al[i][3]=pAl[b1+4];
            }
#pragma unroll
            for (int j=0;j<4;j++){
                int n = wn*32 + j*8 + g;
                u32 bh[2], bl[2];
                bh[0]=pBh[n*20+ks*8+t4]; bh[1]=pBh[n*20+ks*8+4+t4];
                bl[0]=pBl[n*20+ks*8+t4]; bl[1]=pBl[n*20+ks*8+4+t4];
#pragma unroll
                for (int i=0;i<2;i++) mma3(acc[i][j], ah[i], al[i], bh, bl);
            }
        }
    }

#pragma unroll
    for (int i=0;i<2;i++){
#pragma unroll
        for (int j=0;j<4;j++){
            int r0 = m0 + wm*32 + i*16 + g;
            int r1 = r0 + 8;
            int col = n0 + wn*32 + j*8 + t4*2;
            C[(size_t)r0*DM + col    ] = acc[i][j][0] + bias[col];
            C[(size_t)r0*DM + col + 1] = acc[i][j][1] + bias[col+1];
            C[(size_t)r1*DM + col    ] = acc[i][j][2] + bias[col];
            C[(size_t)r1*DM + col + 1] = acc[i][j][3] + bias[col+1];
        }
    }
}

// ---------------------------------------------------------------------------
// Flash attention, cp.async double-buffered K/V, 2 CTAs/SM.
// Block: 128 q rows x 1 head; 8 warps, each 16 rows x full 64-key width.
// ---------------------------------------------------------------------------
#define AS 36                 // smem row stride in u32 words (72 halves)
#define KVW (64*AS)           // words per K/V plane tile
#define ATTN_WORDS (2*128*AS + 2*4*KVW)
#define ATTN_SMEM (ATTN_WORDS*4)

__global__ __launch_bounds__(256,2) void attn_kernel(
    const u32* __restrict__ Qh, const u32* __restrict__ Ql,
    const u32* __restrict__ Kh, const u32* __restrict__ Kl,
    const u32* __restrict__ Vh, const u32* __restrict__ Vl,
    __nv_bfloat16* __restrict__ Ch, __nv_bfloat16* __restrict__ Cl)
{
    extern __shared__ u32 sm[];
    u32* sQh = sm;
    u32* sQl = sm + 128*AS;
    u32* sKV = sm + 2*128*AS;
    const u32 smbase = (u32)__cvta_generic_to_shared(sm);

    const int tid = threadIdx.x, lane = tid&31, wid = tid>>5;
    const int g = lane>>2, t4 = lane&3;
    const int h = blockIdx.y, q0 = blockIdx.x*128;
    const int row = wid*16;

    // async-stage Q planes (group 0)
#pragma unroll
    for (int j=0;j<8;j++){
        int i = tid + j*256;            // 0..2047 chunks
        int plane = i>>10, rem = i&1023;
        int r = rem>>3, c = rem&7;
        const u32* src = (plane ? Ql : Qh) + ((size_t)(h*SQ + q0 + r))*32 + c*4;
        u32 dstw = (plane ? 128*AS : 0) + r*AS + c*4;
        cp16(smbase + dstw*4, src);
    }
    cp_commit();

    // prefetch tile 0 into stage 0
    {
        const int t = 0, st = 0;
        u32 base = 2*128*AS + st*4*KVW;
#pragma unroll
        for (int j=0;j<2;j++){
            int i = tid + j*256;        // 0..511
            int r = i>>3, c = i&7;
            const u32* sk = Kh + ((size_t)(h*SQ + t*64 + r))*32 + c*4;
            cp16(smbase + (base + r*AS + c*4)*4, sk);
            const u32* sl = Kl + ((size_t)(h*SQ + t*64 + r))*32 + c*4;
            cp16(smbase + (base + KVW + r*AS + c*4)*4, sl);
            const u32* vh = Vh + ((size_t)(h*DKH + r))*1024 + t*32 + c*4;
            cp16(smbase + (base + 2*KVW + r*AS + c*4)*4, vh);
            const u32* vl = Vl + ((size_t)(h*DKH + r))*1024 + t*32 + c*4;
            cp16(smbase + (base + 3*KVW + r*AS + c*4)*4, vl);
        }
        cp_commit();
    }

    float oacc[8][4];
#pragma unroll
    for (int j=0;j<8;j++)
#pragma unroll
        for (int e=0;e<4;e++) oacc[j][e]=0.f;
    float m0r=-1e30f, m1r=-1e30f, l0r=0.f, l1r=0.f;

    for (int t=0; t<SQ/64; t++){
        const int st = t & 1;
        if (t+1 < SQ/64) {
            const int nst = (t+1)&1;
            u32 base = 2*128*AS + nst*4*KVW;
#pragma unroll
            for (int j=0;j<2;j++){
                int i = tid + j*256;
                int r = i>>3, c = i&7;
                const u32* sk = Kh + ((size_t)(h*SQ + (t+1)*64 + r))*32 + c*4;
                cp16(smbase + (base + r*AS + c*4)*4, sk);
                const u32* sl = Kl + ((size_t)(h*SQ + (t+1)*64 + r))*32 + c*4;
                cp16(smbase + (base + KVW + r*AS + c*4)*4, sl);
                const u32* vh = Vh + ((size_t)(h*DKH + r))*1024 + (t+1)*32 + c*4;
                cp16(smbase + (base + 2*KVW + r*AS + c*4)*4, vh);
                const u32* vl = Vl + ((size_t)(h*DKH + r))*1024 + (t+1)*32 + c*4;
                cp16(smbase + (base + 3*KVW + r*AS + c*4)*4, vl);
            }
            cp_commit();
            cp_wait<1>();      // tile t (and Q) arrived
        } else {
            cp_wait<0>();      // last tile fully arrived
        }
        __syncthreads();

        u32* sKh = sKV + st*4*KVW;
        u32* sKl = sKh + KVW;
        u32* sVh = sKl + KVW;
        u32* sVl = sVh + KVW;

        // scores: 16 rows x 64 keys per warp
        float sc[8][4];
#pragma unroll
        for (int j=0;j<8;j++)
#pragma unroll
            for (int e=0;e<4;e++) sc[j][e]=0.f;
#pragma unroll
        for (int ks=0;ks<4;ks++){
            u32 qh[4], ql[4];
            int b0 = (row+g)*AS + ks*8 + t4;
            int b1 = (row+g+8)*AS + ks*8 + t4;
            qh[0]=sQh[b0]; qh[1]=sQh[b1]; qh[2]=sQh[b0+4]; qh[3]=sQh[b1+4];
            ql[0]=sQl[b0]; ql[1]=sQl[b1]; ql[2]=sQl[b0+4]; ql[3]=sQl[b1+4];
#pragma unroll
            for (int j=0;j<8;j++){
                int n=(j*8+g)*AS + ks*8 + t4;
                u32 bh[2], bl[2];
                bh[0]=sKh[n]; bh[1]=sKh[n+4];
                bl[0]=sKl[n]; bl[1]=sKl[n+4];
                mma3(sc[j], qh, ql, bh, bl);
            }
        }

        // online softmax (Q pre-scaled by 0.125 in projection)
        float tm0=-1e30f, tm1=-1e30f;
#pragma unroll
        for (int j=0;j<8;j++){
            tm0 = fmaxf(tm0, fmaxf(sc[j][0], sc[j][1]));
            tm1 = fmaxf(tm1, fmaxf(sc[j][2], sc[j][3]));
        }
        tm0 = fmaxf(tm0, __shfl_xor_sync(0xffffffffu, tm0, 1));
        tm0 = fmaxf(tm0, __shfl_xor_sync(0xffffffffu, tm0, 2));
        tm1 = fmaxf(tm1, __shfl_xor_sync(0xffffffffu, tm1, 1));
        tm1 = fmaxf(tm1, __shfl_xor_sync(0xffffffffu, tm1, 2));
        float mn0 = fmaxf(m0r, tm0), mn1 = fmaxf(m1r, tm1);
        float c0 = __expf(m0r - mn0), c1 = __expf(m1r - mn1);
        float rs0=0.f, rs1=0.f;
#pragma unroll
        for (int j=0;j<8;j++){
            sc[j][0]=__expf(sc[j][0]-mn0); sc[j][1]=__expf(sc[j][1]-mn0);
            sc[j][2]=__expf(sc[j][2]-mn1); sc[j][3]=__expf(sc[j][3]-mn1);
            rs0 += sc[j][0]+sc[j][1]; rs1 += sc[j][2]+sc[j][3];
        }
        rs0 += __shfl_xor_sync(0xffffffffu, rs0, 1);
        rs0 += __shfl_xor_sync(0xffffffffu, rs0, 2);
        rs1 += __shfl_xor_sync(0xffffffffu, rs1, 1);
        rs1 += __shfl_xor_sync(0xffffffffu, rs1, 2);
        l0r = l0r*c0 + rs0; l1r = l1r*c1 + rs1;
        m0r = mn0; m1r = mn1;
#pragma unroll
        for (int j=0;j<8;j++){
            oacc[j][0]*=c0; oacc[j][1]*=c0; oacc[j][2]*=c1; oacc[j][3]*=c1;
        }

        // PV: P frags built in-register from score frags
#pragma unroll
        for (int s=0;s<4;s++){
            u32 ph[4], pl[4];
            split_pack(sc[2*s  ][0], sc[2*s  ][1], ph[0], pl[0]);
            split_pack(sc[2*s  ][2], sc[2*s  ][3], ph[1], pl[1]);
            split_pack(sc[2*s+1][0], sc[2*s+1][1], ph[2], pl[2]);
            split_pack(sc[2*s+1][2], sc[2*s+1][3], ph[3], pl[3]);
#pragma unroll
            for (int j=0;j<8;j++){
                int n=(j*8+g)*AS + s*8 + t4;
                u32 bh[2], bl[2];
                bh[0]=sVh[n]; bh[1]=sVh[n+4];
                bl[0]=sVl[n]; bl[1]=sVl[n+4];
                mma3(oacc[j], ph, pl, bh, bl);
            }
        }
        __syncthreads();   // all warps done with stage st before it is refilled
    }

    // epilogue
    float inv0 = 1.f/l0r, inv1 = 1.f/l1r;
    int r0 = q0 + row + g, r1 = r0+8;
#pragma unroll
    for (int j=0;j<8;j++){
        int col = h*DKH + j*8 + t4*2;
        u32 hh, ll;
        split_pack(oacc[j][0]*inv0, oacc[j][1]*inv0, hh, ll);
        ((u32*)Ch)[(r0*NHID + col)>>1] = hh;
        ((u32*)Cl)[(r0*NHID + col)>>1] = ll;
        split_pack(oacc[j][2]*inv1, oacc[j][3]*inv1, hh, ll);
        ((u32*)Ch)[(r1*NHID + col)>>1] = hh;
        ((u32*)Cl)[(r1*NHID + col)>>1] = ll;
    }
}

// ---------------------------------------------------------------------------
extern "C" void kernel_launch(void* const* d_in, const int* in_sizes, int n_in,
                              void* d_out, int out_size)
{
    const float* Q  = (const float*)d_in[0];
    const float* K  = (const float*)d_in[1];
    const float* V  = (const float*)d_in[2];
    const float* Wq = (const float*)d_in[3];
    const float* bq = (const float*)d_in[4];
    const float* Wk = (const float*)d_in[5];
    const float* bk = (const float*)d_in[6];
    const float* Wv = (const float*)d_in[7];
    const float* bv = (const float*)d_in[8];
    const float* Wo = (const float*)d_in[9];
    const float* bo = (const float*)d_in[10];
    float* out = (float*)d_out;

    __nv_bfloat16 *qh,*ql,*kh,*kl,*vth,*vtl,*ch,*cl;
    cudaGetSymbolAddress((void**)&qh,  g_qh);
    cudaGetSymbolAddress((void**)&ql,  g_ql);
    cudaGetSymbolAddress((void**)&kh,  g_kh);
    cudaGetSymbolAddress((void**)&kl,  g_kl);
    cudaGetSymbolAddress((void**)&vth, g_vth);
    cudaGetSymbolAddress((void**)&vtl, g_vtl);
    cudaGetSymbolAddress((void**)&ch,  g_ch);
    cudaGetSymbolAddress((void**)&cl,  g_cl);

    cudaFuncSetAttribute(attn_kernel,
                         cudaFuncAttributeMaxDynamicSharedMemorySize, ATTN_SMEM);

    dim3 pg(NH, SQ/128, 3);       // (16, 16, 3) — fused Q/K/V projections
    proj_kernel<<<pg, 256>>>(Q, K, V, Wq, Wk, Wv, bq, bk, bv,
                             qh, ql, kh, kl, vth, vtl);

    dim3 ag(SQ/128, NH);          // (16, 16)
    attn_kernel<<<ag, 256, ATTN_SMEM>>>((u32*)qh,(u32*)ql,(u32*)kh,(u32*)kl,
                                        (u32*)vth,(u32*)vtl, ch, cl);

    dim3 og(DM/64, SQ/128);       // (16, 16)
    out_kernel<<<og, 256>>>((u32*)ch,(u32*)cl, Wo, bo, out);
}

// round 6
// speedup vs baseline: 3.4323x; 1.4463x over previous
#include <cuda_runtime.h>
#include <cuda_bf16.h>

#define SQ 2048
#define DM 1024
#define NH 16
#define DKH 64
#define NHID 1024

typedef unsigned int u32;
typedef unsigned short u16;

// ---------------- scratch planes (bf16 hi/lo) ----------------
__device__ u16 g_xh[3*SQ*DM];        // split activations (Q,K,V inputs)
__device__ u16 g_xl[3*SQ*DM];
__device__ u16 g_wth[3*NH*DKH*DM];   // split transposed QKV weights [(which*16+h)*64+n][d]
__device__ u16 g_wtl[3*NH*DKH*DM];
__device__ u16 g_woth[NHID*DM];      // split transposed Wo [n][k]
__device__ u16 g_wotl[NHID*DM];
__device__ u16 g_qh[NH*SQ*DKH];      // projected q/k planes [h][s][64]
__device__ u16 g_ql[NH*SQ*DKH];
__device__ u16 g_kh[NH*SQ*DKH];
__device__ u16 g_kl[NH*SQ*DKH];
__device__ u16 g_vth[NH*DKH*SQ];     // projected V transposed [h][d][s]
__device__ u16 g_vtl[NH*DKH*SQ];
__device__ u16 g_ch[SQ*NHID];        // concat planes [s][1024]
__device__ u16 g_cl[SQ*NHID];

// ---------------- helpers ----------------
__device__ __forceinline__ void split1(float x, u16& h, u16& l) {
    __nv_bfloat16 hb = __float2bfloat16(x);
    h = __bfloat16_as_ushort(hb);
    l = __bfloat16_as_ushort(__float2bfloat16(x - __bfloat162float(hb)));
}
__device__ __forceinline__ void split_pack(float x0, float x1, u32& h, u32& l) {
    u16 h0,l0,h1,l1;
    split1(x0,h0,l0); split1(x1,h1,l1);
    h = ((u32)h1<<16)|h0; l = ((u32)l1<<16)|l0;
}
__device__ __forceinline__ void mma_bf16(float* c, const u32* a, const u32* b) {
    asm volatile(
      "mma.sync.aligned.m16n8k16.row.col.f32.bf16.bf16.f32 "
      "{%0,%1,%2,%3}, {%4,%5,%6,%7}, {%8,%9}, {%0,%1,%2,%3};\n"
      : "+f"(c[0]), "+f"(c[1]), "+f"(c[2]), "+f"(c[3])
      : "r"(a[0]), "r"(a[1]), "r"(a[2]), "r"(a[3]), "r"(b[0]), "r"(b[1]));
}
__device__ __forceinline__ void mma3(float* c, const u32* ah, const u32* al,
                                     const u32* bh, const u32* bl) {
    mma_bf16(c, ah, bh);
    mma_bf16(c, ah, bl);
    mma_bf16(c, al, bh);
}
__device__ __forceinline__ void cp16(u32 dst_smem, const void* src) {
    asm volatile("cp.async.cg.shared.global [%0], [%1], 16;\n"
                 :: "r"(dst_smem), "l"(src));
}
__device__ __forceinline__ void cp_commit() {
    asm volatile("cp.async.commit_group;\n");
}
template<int N> __device__ __forceinline__ void cp_wait() {
    asm volatile("cp.async.wait_group %0;\n" :: "n"(N));
}
__device__ __forceinline__ void ldsm4(u32& r0, u32& r1, u32& r2, u32& r3, u32 saddr) {
    asm volatile("ldmatrix.sync.aligned.m8n8.x4.shared.b16 {%0,%1,%2,%3}, [%4];\n"
                 : "=r"(r0), "=r"(r1), "=r"(r2), "=r"(r3) : "r"(saddr));
}

// ---------------------------------------------------------------------------
// Pre-pass 1: split activations (Q|K|V) -> bf16 hi/lo planes. 8 floats/thread.
// ---------------------------------------------------------------------------
__global__ __launch_bounds__(256) void asplit_kernel(
    const float* __restrict__ Q, const float* __restrict__ K,
    const float* __restrict__ V, u16* __restrict__ oh, u16* __restrict__ ol)
{
    size_t base = ((size_t)blockIdx.x*256 + threadIdx.x)*8;
    int which = (int)(base >> 21);             // 2M elements per input
    size_t rem = base & 2097151;
    const float* in = (which==0)?Q:(which==1)?K:V;
    float4 f0 = *(const float4*)(in+rem);
    float4 f1 = *(const float4*)(in+rem+4);
    u32 h0,l0,h1,l1,h2,l2,h3,l3;
    split_pack(f0.x,f0.y,h0,l0);
    split_pack(f0.z,f0.w,h1,l1);
    split_pack(f1.x,f1.y,h2,l2);
    split_pack(f1.z,f1.w,h3,l3);
    *(uint4*)(oh + base) = make_uint4(h0,h1,h2,h3);
    *(uint4*)(ol + base) = make_uint4(l0,l1,l2,l3);
}

// ---------------------------------------------------------------------------
// Pre-pass 2: transpose+split QKV weights. in: W[h][d=1024][k=64] ->
// out planes [(which*16+h)*64 + k][d].
// ---------------------------------------------------------------------------
__global__ void wsplit_qkv_kernel(
    const float* __restrict__ Wq, const float* __restrict__ Wk,
    const float* __restrict__ Wv, u16* __restrict__ oh, u16* __restrict__ ol)
{
    __shared__ float t[32][33];
    int z = blockIdx.z, which = z>>4, h = z&15;
    const float* in = ((which==0)?Wq:(which==1)?Wk:Wv) + (size_t)h*DM*DKH;
    int d0 = blockIdx.x*32, k0 = blockIdx.y*32;
    int tx = threadIdx.x, ty = threadIdx.y;
    t[ty][tx] = in[(size_t)(d0+ty)*DKH + k0+tx];
    __syncthreads();
    float v = t[tx][ty];                      // = in[d0+tx][k0+ty]
    u16 hh,ll; split1(v,hh,ll);
    size_t o = ((size_t)z*DKH + k0+ty)*DM + d0+tx;
    oh[o]=hh; ol[o]=ll;
}

// Pre-pass 3: transpose+split Wo [k=1024][n=1024] -> planes [n][k]
__global__ void wsplit_wo_kernel(
    const float* __restrict__ Wo, u16* __restrict__ oh, u16* __restrict__ ol)
{
    __shared__ float t[32][33];
    int k0 = blockIdx.x*32, n0 = blockIdx.y*32;
    int tx = threadIdx.x, ty = threadIdx.y;
    t[ty][tx] = Wo[(size_t)(k0+ty)*DM + n0+tx];
    __syncthreads();
    float v = t[tx][ty];                      // = Wo[k0+tx][n0+ty]
    u16 hh,ll; split1(v,hh,ll);
    size_t o = ((size_t)(n0+ty))*DM + k0+tx;
    oh[o]=hh; ol[o]=ll;
}

// ---------------------------------------------------------------------------
// GEMM smem geometry (shared by proj2 / out2)
// stage: Ah[128][36w] Al Bh[64][36w] Bl  (72-half rows, 16B aligned, LDSM
// conflict-free: 144B row stride -> 8 rows hit distinct bank quads)
// ---------------------------------------------------------------------------
#define GAS 36
#define A_WORDS (128*GAS)            // 4608
#define B_WORDS (64*GAS)             // 2304
#define GSTG (2*A_WORDS + 2*B_WORDS) // 13824 words/stage
#define GEMM_SMEM (2*GSTG*4)         // 110592 B

// ---------------------------------------------------------------------------
// Fused projection GEMM v2: pure-bf16 planes, cp.async double buffer, LDSM.
// Block 128(M) x 64(N=head), BK=64. z selects Q/K/V.
// ---------------------------------------------------------------------------
__global__ __launch_bounds__(256) void proj2_kernel(
    const u32* __restrict__ Xh, const u32* __restrict__ Xl,
    const u32* __restrict__ Wh, const u32* __restrict__ Wl,
    const float* __restrict__ bq, const float* __restrict__ bk,
    const float* __restrict__ bv,
    u16* __restrict__ oqh, u16* __restrict__ oql,
    u16* __restrict__ okh, u16* __restrict__ okl,
    u16* __restrict__ ovh, u16* __restrict__ ovl)
{
    extern __shared__ u32 sm[];
    const u32 smb = (u32)__cvta_generic_to_shared(sm);
    const int tid=threadIdx.x, lane=tid&31, wid=tid>>5;
    const int g=lane>>2, t4=lane&3;
    const int wm=wid>>1, wn=wid&1;
    const int which=blockIdx.z, head=blockIdx.x, m0=blockIdx.y*128;

    const u32* aH = Xh + (size_t)which*(SQ*DM/2);
    const u32* aL = Xl + (size_t)which*(SQ*DM/2);
    const int zrow = (which*NH + head)*DKH;

    float acc[2][4][4];
#pragma unroll
    for (int i=0;i<2;i++)
#pragma unroll
      for (int j=0;j<4;j++)
#pragma unroll
        for (int e=0;e<4;e++) acc[i][j][e]=0.f;

    auto issue = [&](int kt, int st){
        int k0w = kt*32;
        u32 base = st*GSTG;
#pragma unroll
        for (int j=0;j<8;j++){
            int i = tid + j*256;
            int pl = i>>10, rem = i&1023;
            int r = rem>>3, c = rem&7;
            const u32* src = (pl? aL : aH) + (size_t)(m0+r)*512 + k0w + c*4;
            cp16(smb + (base + pl*A_WORDS + r*GAS + c*4)*4, src);
        }
#pragma unroll
        for (int j=0;j<4;j++){
            int i = tid + j*256;
            int pl = i>>9, rem = i&511;
            int r = rem>>3, c = rem&7;
            const u32* src = (pl? Wl : Wh) + (size_t)(zrow+r)*512 + k0w + c*4;
            cp16(smb + (base + 2*A_WORDS + pl*B_WORDS + r*GAS + c*4)*4, src);
        }
        cp_commit();
    };

    issue(0,0);
    for (int kt=0; kt<16; kt++){
        int st = kt&1;
        if (kt+1 < 16){ issue(kt+1, st^1); cp_wait<1>(); }
        else cp_wait<0>();
        __syncthreads();

        u32 base = st*GSTG;
#pragma unroll
        for (int ks=0;ks<4;ks++){
            u32 ah[2][4], al[2][4];
#pragma unroll
            for (int i=0;i<2;i++){
                int rowb = wm*32 + i*16 + (lane&15);
                u32 w = base + rowb*GAS + ks*8 + (lane>>4)*4;
                ldsm4(ah[i][0],ah[i][1],ah[i][2],ah[i][3], smb + w*4);
                ldsm4(al[i][0],al[i][1],al[i][2],al[i][3], smb + (w+A_WORDS)*4);
            }
#pragma unroll
            for (int p=0;p<2;p++){
                int nb = wn*32 + p*16 + ((lane>>4)<<3) + (lane&7);
                u32 w = base + 2*A_WORDS + nb*GAS + ks*8 + ((lane>>3)&1)*4;
                u32 bh[4], bl[4];
                ldsm4(bh[0],bh[1],bh[2],bh[3], smb + w*4);
                ldsm4(bl[0],bl[1],bl[2],bl[3], smb + (w+B_WORDS)*4);
#pragma unroll
                for (int i=0;i<2;i++){
                    mma3(acc[i][2*p  ], ah[i], al[i], bh+0, bl+0);
                    mma3(acc[i][2*p+1], ah[i], al[i], bh+2, bl+2);
                }
            }
        }
        __syncthreads();
    }

    // epilogue
    const float* bias = (which==0)?bq:(which==1)?bk:bv;
    u16* outH = (which==0)?oqh:(which==1)?okh:ovh;
    u16* outL = (which==0)?oql:(which==1)?okl:ovl;
    const int transposed = (which==2);
    const float osc = (which==0)?0.125f:1.f;
#pragma unroll
    for (int i=0;i<2;i++){
#pragma unroll
        for (int j=0;j<4;j++){
            int r0 = m0 + wm*32 + i*16 + g;
            int r1 = r0 + 8;
            int col = wn*32 + j*8 + t4*2;
            float b0f = bias[head*DKH + col];
            float b1f = bias[head*DKH + col + 1];
            float v0 = (acc[i][j][0] + b0f) * osc;
            float v1 = (acc[i][j][1] + b1f) * osc;
            float v2 = (acc[i][j][2] + b0f) * osc;
            float v3 = (acc[i][j][3] + b1f) * osc;
            if (!transposed) {
                u32 h,l;
                split_pack(v0,v1,h,l);
                ((u32*)outH)[(head*SQ + r0)*32 + (col>>1)] = h;
                ((u32*)outL)[(head*SQ + r0)*32 + (col>>1)] = l;
                split_pack(v2,v3,h,l);
                ((u32*)outH)[(head*SQ + r1)*32 + (col>>1)] = h;
                ((u32*)outL)[(head*SQ + r1)*32 + (col>>1)] = l;
            } else {
                u16 h,l;
                split1(v0,h,l); outH[(head*DKH+col  )*SQ + r0]=h; outL[(head*DKH+col  )*SQ + r0]=l;
                split1(v1,h,l); outH[(head*DKH+col+1)*SQ + r0]=h; outL[(head*DKH+col+1)*SQ + r0]=l;
                split1(v2,h,l); outH[(head*DKH+col  )*SQ + r1]=h; outL[(head*DKH+col  )*SQ + r1]=l;
                split1(v3,h,l); outH[(head*DKH+col+1)*SQ + r1]=h; outL[(head*DKH+col+1)*SQ + r1]=l;
            }
        }
    }
}

// ---------------------------------------------------------------------------
// Output projection v2: A = concat planes, B = transposed-split Wo.
// ---------------------------------------------------------------------------
__global__ __launch_bounds__(256) void out2_kernel(
    const u32* __restrict__ Ah, const u32* __restrict__ Al,
    const u32* __restrict__ Bh, const u32* __restrict__ Bl,
    const float* __restrict__ bias, float* __restrict__ C)
{
    extern __shared__ u32 sm[];
    const u32 smb = (u32)__cvta_generic_to_shared(sm);
    const int tid=threadIdx.x, lane=tid&31, wid=tid>>5;
    const int g=lane>>2, t4=lane&3;
    const int wm=wid>>1, wn=wid&1;
    const int n0=blockIdx.x*64, m0=blockIdx.y*128;

    float acc[2][4][4];
#pragma unroll
    for (int i=0;i<2;i++)
#pragma unroll
      for (int j=0;j<4;j++)
#pragma unroll
        for (int e=0;e<4;e++) acc[i][j][e]=0.f;

    auto issue = [&](int kt, int st){
        int k0w = kt*32;
        u32 base = st*GSTG;
#pragma unroll
        for (int j=0;j<8;j++){
            int i = tid + j*256;
            int pl = i>>10, rem = i&1023;
            int r = rem>>3, c = rem&7;
            const u32* src = (pl? Al : Ah) + (size_t)(m0+r)*512 + k0w + c*4;
            cp16(smb + (base + pl*A_WORDS + r*GAS + c*4)*4, src);
        }
#pragma unroll
        for (int j=0;j<4;j++){
            int i = tid + j*256;
            int pl = i>>9, rem = i&511;
            int r = rem>>3, c = rem&7;
            const u32* src = (pl? Bl : Bh) + (size_t)(n0+r)*512 + k0w + c*4;
            cp16(smb + (base + 2*A_WORDS + pl*B_WORDS + r*GAS + c*4)*4, src);
        }
        cp_commit();
    };

    issue(0,0);
    for (int kt=0; kt<16; kt++){
        int st = kt&1;
        if (kt+1 < 16){ issue(kt+1, st^1); cp_wait<1>(); }
        else cp_wait<0>();
        __syncthreads();

        u32 base = st*GSTG;
#pragma unroll
        for (int ks=0;ks<4;ks++){
            u32 ah[2][4], al[2][4];
#pragma unroll
            for (int i=0;i<2;i++){
                int rowb = wm*32 + i*16 + (lane&15);
                u32 w = base + rowb*GAS + ks*8 + (lane>>4)*4;
                ldsm4(ah[i][0],ah[i][1],ah[i][2],ah[i][3], smb + w*4);
                ldsm4(al[i][0],al[i][1],al[i][2],al[i][3], smb + (w+A_WORDS)*4);
            }
#pragma unroll
            for (int p=0;p<2;p++){
                int nb = wn*32 + p*16 + ((lane>>4)<<3) + (lane&7);
                u32 w = base + 2*A_WORDS + nb*GAS + ks*8 + ((lane>>3)&1)*4;
                u32 bh[4], bl[4];
                ldsm4(bh[0],bh[1],bh[2],bh[3], smb + w*4);
                ldsm4(bl[0],bl[1],bl[2],bl[3], smb + (w+B_WORDS)*4);
#pragma unroll
                for (int i=0;i<2;i++){
                    mma3(acc[i][2*p  ], ah[i], al[i], bh+0, bl+0);
                    mma3(acc[i][2*p+1], ah[i], al[i], bh+2, bl+2);
                }
            }
        }
        __syncthreads();
    }

#pragma unroll
    for (int i=0;i<2;i++){
#pragma unroll
        for (int j=0;j<4;j++){
            int r0 = m0 + wm*32 + i*16 + g;
            int r1 = r0 + 8;
            int col = n0 + wn*32 + j*8 + t4*2;
            C[(size_t)r0*DM + col    ] = acc[i][j][0] + bias[col];
            C[(size_t)r0*DM + col + 1] = acc[i][j][1] + bias[col+1];
            C[(size_t)r1*DM + col    ] = acc[i][j][2] + bias[col];
            C[(size_t)r1*DM + col + 1] = acc[i][j][3] + bias[col+1];
        }
    }
}

// ---------------------------------------------------------------------------
// Flash attention: cp.async double-buffered K/V, LDSM fragments, 2 CTAs/SM.
// ---------------------------------------------------------------------------
#define AS 36
#define KVW (64*AS)
#define ATTN_WORDS (2*128*AS + 2*4*KVW)
#define ATTN_SMEM (ATTN_WORDS*4)

__global__ __launch_bounds__(256,2) void attn_kernel(
    const u32* __restrict__ Qh, const u32* __restrict__ Ql,
    const u32* __restrict__ Kh, const u32* __restrict__ Kl,
    const u32* __restrict__ Vh, const u32* __restrict__ Vl,
    u16* __restrict__ Ch, u16* __restrict__ Cl)
{
    extern __shared__ u32 sm[];
    const u32 smb = (u32)__cvta_generic_to_shared(sm);

    const int tid = threadIdx.x, lane = tid&31, wid = tid>>5;
    const int g = lane>>2, t4 = lane&3;
    const int h = blockIdx.y, q0 = blockIdx.x*128;
    const int row = wid*16;

    // async-stage Q planes
#pragma unroll
    for (int j=0;j<8;j++){
        int i = tid + j*256;
        int plane = i>>10, rem = i&1023;
        int r = rem>>3, c = rem&7;
        const u32* src = (plane ? Ql : Qh) + ((size_t)(h*SQ + q0 + r))*32 + c*4;
        cp16(smb + ((plane ? 128*AS : 0) + r*AS + c*4)*4, src);
    }
    cp_commit();

    auto issueKV = [&](int t, int st){
        u32 base = 2*128*AS + st*4*KVW;
#pragma unroll
        for (int j=0;j<2;j++){
            int i = tid + j*256;
            int r = i>>3, c = i&7;
            cp16(smb + (base +           r*AS + c*4)*4, Kh + ((size_t)(h*SQ + t*64 + r))*32 + c*4);
            cp16(smb + (base +   KVW +   r*AS + c*4)*4, Kl + ((size_t)(h*SQ + t*64 + r))*32 + c*4);
            cp16(smb + (base + 2*KVW +   r*AS + c*4)*4, Vh + ((size_t)(h*DKH + r))*1024 + t*32 + c*4);
            cp16(smb + (base + 3*KVW +   r*AS + c*4)*4, Vl + ((size_t)(h*DKH + r))*1024 + t*32 + c*4);
        }
        cp_commit();
    };
    issueKV(0,0);

    float oacc[8][4];
#pragma unroll
    for (int j=0;j<8;j++)
#pragma unroll
        for (int e=0;e<4;e++) oacc[j][e]=0.f;
    float m0r=-1e30f, m1r=-1e30f, l0r=0.f, l1r=0.f;

    for (int t=0; t<SQ/64; t++){
        const int st = t & 1;
        if (t+1 < SQ/64) { issueKV(t+1, st^1); cp_wait<1>(); }
        else cp_wait<0>();
        __syncthreads();

        u32 kbase = 2*128*AS + st*4*KVW;
        u32 vbase = kbase + 2*KVW;

        // scores
        float sc[8][4];
#pragma unroll
        for (int j=0;j<8;j++)
#pragma unroll
            for (int e=0;e<4;e++) sc[j][e]=0.f;
#pragma unroll
        for (int ks=0;ks<4;ks++){
            u32 qh[4], ql[4];
            int rowb = row + (lane&15);
            u32 wq = rowb*AS + ks*8 + (lane>>4)*4;
            ldsm4(qh[0],qh[1],qh[2],qh[3], smb + wq*4);
            ldsm4(ql[0],ql[1],ql[2],ql[3], smb + (wq + 128*AS)*4);
#pragma unroll
            for (int p=0;p<4;p++){
                int nb = p*16 + ((lane>>4)<<3) + (lane&7);
                u32 w = kbase + nb*AS + ks*8 + ((lane>>3)&1)*4;
                u32 bh[4], bl[4];
                ldsm4(bh[0],bh[1],bh[2],bh[3], smb + w*4);
                ldsm4(bl[0],bl[1],bl[2],bl[3], smb + (w+KVW)*4);
                mma3(sc[2*p  ], qh, ql, bh+0, bl+0);
                mma3(sc[2*p+1], qh, ql, bh+2, bl+2);
            }
        }

        // online softmax (Q pre-scaled by 0.125)
        float tm0=-1e30f, tm1=-1e30f;
#pragma unroll
        for (int j=0;j<8;j++){
            tm0 = fmaxf(tm0, fmaxf(sc[j][0], sc[j][1]));
            tm1 = fmaxf(tm1, fmaxf(sc[j][2], sc[j][3]));
        }
        tm0 = fmaxf(tm0, __shfl_xor_sync(0xffffffffu, tm0, 1));
        tm0 = fmaxf(tm0, __shfl_xor_sync(0xffffffffu, tm0, 2));
        tm1 = fmaxf(tm1, __shfl_xor_sync(0xffffffffu, tm1, 1));
        tm1 = fmaxf(tm1, __shfl_xor_sync(0xffffffffu, tm1, 2));
        float mn0 = fmaxf(m0r, tm0), mn1 = fmaxf(m1r, tm1);
        float c0 = __expf(m0r - mn0), c1 = __expf(m1r - mn1);
        float rs0=0.f, rs1=0.f;
#pragma unroll
        for (int j=0;j<8;j++){
            sc[j][0]=__expf(sc[j][0]-mn0); sc[j][1]=__expf(sc[j][1]-mn0);
            sc[j][2]=__expf(sc[j][2]-mn1); sc[j][3]=__expf(sc[j][3]-mn1);
            rs0 += sc[j][0]+sc[j][1]; rs1 += sc[j][2]+sc[j][3];
        }
        rs0 += __shfl_xor_sync(0xffffffffu, rs0, 1);
        rs0 += __shfl_xor_sync(0xffffffffu, rs0, 2);
        rs1 += __shfl_xor_sync(0xffffffffu, rs1, 1);
        rs1 += __shfl_xor_sync(0xffffffffu, rs1, 2);
        l0r = l0r*c0 + rs0; l1r = l1r*c1 + rs1;
        m0r = mn0; m1r = mn1;
#pragma unroll
        for (int j=0;j<8;j++){
            oacc[j][0]*=c0; oacc[j][1]*=c0; oacc[j][2]*=c1; oacc[j][3]*=c1;
        }

        // PV
#pragma unroll
        for (int s=0;s<4;s++){
            u32 ph[4], pl[4];
            split_pack(sc[2*s  ][0], sc[2*s  ][1], ph[0], pl[0]);
            split_pack(sc[2*s  ][2], sc[2*s  ][3], ph[1], pl[1]);
            split_pack(sc[2*s+1][0], sc[2*s+1][1], ph[2], pl[2]);
            split_pack(sc[2*s+1][2], sc[2*s+1][3], ph[3], pl[3]);
#pragma unroll
            for (int p=0;p<4;p++){
                int nb = p*16 + ((lane>>4)<<3) + (lane&7);
                u32 w = vbase + nb*AS + s*8 + ((lane>>3)&1)*4;
                u32 bh[4], bl[4];
                ldsm4(bh[0],bh[1],bh[2],bh[3], smb + w*4);
                ldsm4(bl[0],bl[1],bl[2],bl[3], smb + (w+KVW)*4);
                mma3(oacc[2*p  ], ph, pl, bh+0, bl+0);
                mma3(oacc[2*p+1], ph, pl, bh+2, bl+2);
            }
        }
        __syncthreads();
    }

    // epilogue -> concat planes
    float inv0 = 1.f/l0r, inv1 = 1.f/l1r;
    int r0 = q0 + row + g, r1 = r0+8;
#pragma unroll
    for (int j=0;j<8;j++){
        int col = h*DKH + j*8 + t4*2;
        u32 hh, ll;
        split_pack(oacc[j][0]*inv0, oacc[j][1]*inv0, hh, ll);
        ((u32*)Ch)[(r0*NHID + col)>>1] = hh;
        ((u32*)Cl)[(r0*NHID + col)>>1] = ll;
        split_pack(oacc[j][2]*inv1, oacc[j][3]*inv1, hh, ll);
        ((u32*)Ch)[(r1*NHID + col)>>1] = hh;
        ((u32*)Cl)[(r1*NHID + col)>>1] = ll;
    }
}

// ---------------------------------------------------------------------------
extern "C" void kernel_launch(void* const* d_in, const int* in_sizes, int n_in,
                              void* d_out, int out_size)
{
    const float* Q  = (const float*)d_in[0];
    const float* K  = (const float*)d_in[1];
    const float* V  = (const float*)d_in[2];
    const float* Wq = (const float*)d_in[3];
    const float* bq = (const float*)d_in[4];
    const float* Wk = (const float*)d_in[5];
    const float* bk = (const float*)d_in[6];
    const float* Wv = (const float*)d_in[7];
    const float* bv = (const float*)d_in[8];
    const float* Wo = (const float*)d_in[9];
    const float* bo = (const float*)d_in[10];
    float* out = (float*)d_out;

    u16 *xh,*xl,*wth,*wtl,*woth,*wotl;
    u16 *qh,*ql,*kh,*kl,*vth,*vtl,*ch,*cl;
    cudaGetSymbolAddress((void**)&xh,   g_xh);
    cudaGetSymbolAddress((void**)&xl,   g_xl);
    cudaGetSymbolAddress((void**)&wth,  g_wth);
    cudaGetSymbolAddress((void**)&wtl,  g_wtl);
    cudaGetSymbolAddress((void**)&woth, g_woth);
    cudaGetSymbolAddress((void**)&wotl, g_wotl);
    cudaGetSymbolAddress((void**)&qh,   g_qh);
    cudaGetSymbolAddress((void**)&ql,   g_ql);
    cudaGetSymbolAddress((void**)&kh,   g_kh);
    cudaGetSymbolAddress((void**)&kl,   g_kl);
    cudaGetSymbolAddress((void**)&vth,  g_vth);
    cudaGetSymbolAddress((void**)&vtl,  g_vtl);
    cudaGetSymbolAddress((void**)&ch,   g_ch);
    cudaGetSymbolAddress((void**)&cl,   g_cl);

    cudaFuncSetAttribute(proj2_kernel,
                         cudaFuncAttributeMaxDynamicSharedMemorySize, GEMM_SMEM);
    cudaFuncSetAttribute(out2_kernel,
                         cudaFuncAttributeMaxDynamicSharedMemorySize, GEMM_SMEM);
    cudaFuncSetAttribute(attn_kernel,
                         cudaFuncAttributeMaxDynamicSharedMemorySize, ATTN_SMEM);

    // pre-passes: split activations + weights
    asplit_kernel<<<3*SQ*DM/(256*8), 256>>>(Q, K, V, xh, xl);
    wsplit_qkv_kernel<<<dim3(32,2,48), dim3(32,32)>>>(Wq, Wk, Wv, wth, wtl);
    wsplit_wo_kernel<<<dim3(32,32), dim3(32,32)>>>(Wo, woth, wotl);

    // projections (fused Q/K/V)
    dim3 pg(NH, SQ/128, 3);
    proj2_kernel<<<pg, 256, GEMM_SMEM>>>((u32*)xh,(u32*)xl,(u32*)wth,(u32*)wtl,
                                         bq, bk, bv,
                                         qh, ql, kh, kl, vth, vtl);

    dim3 ag(SQ/128, NH);
    attn_kernel<<<ag, 256, ATTN_SMEM>>>((u32*)qh,(u32*)ql,(u32*)kh,(u32*)kl,
                                        (u32*)vth,(u32*)vtl, ch, cl);

    dim3 og(DM/64, SQ/128);
    out2_kernel<<<og, 256, GEMM_SMEM>>>((u32*)ch,(u32*)cl,(u32*)woth,(u32*)wotl,
                                        bo, out);
}